// round 15
// baseline (speedup 1.0000x reference)
#include <cuda_runtime.h>
#include <cuda_bf16.h>
#include <stdint.h>

#define THREADS 256
#define ITEMS   8
#define CHUNK   (THREADS * ITEMS)   // 2048
#define NWARPS  (THREADS / 32)      // 8
#define CAPR    95                  // staged rows per warp-chunk (16B padded)
#define STREG   9                   // 9*32 = 288 >= 3*CAPR floats
#define PADMASK 0x00FF0000u

__global__ __launch_bounds__(THREADS, 2)
void traj_scan_kernel(const int*   __restrict__ states,
                      const float* __restrict__ e0s,
                      const float* __restrict__ speed0,
                      const float* __restrict__ speed1,
                      const float* __restrict__ x0,
                      float*       __restrict__ X,
                      int T, int P)
{
    __shared__ __align__(16) float smb[4][NWARPS][CAPR * 4];  // 48640 B
    __shared__ float s_a[NWARPS][5];
    __shared__ float s_b[NWARPS][3];

    const int b = blockIdx.x;
    const int*   srow = states + (size_t)b * T;
    const float* erow = e0s    + (size_t)b * (T + 1) * 3;
    float*       xrow = X      + (size_t)b * T * 3;

    const float sp0 = speed0[b], sp1 = speed1[b];
    const float ox = x0[3*b+0], oy = x0[3*b+1], oz = x0[3*b+2];
    const float DT = 0.1f;
    const int tid = threadIdx.x, lane = tid & 31, wid = tid >> 5;

    #define LDST(c, A, B) do {                                                \
        const int _t0 = (c) * CHUNK + tid * ITEMS;                            \
        if (_t0 + ITEMS <= T) {                                               \
            A = *reinterpret_cast<const int4*>(srow + _t0);                   \
            B = *reinterpret_cast<const int4*>(srow + _t0 + 4);               \
        } else {                                                              \
            int _s[8] = {1,1,1,1,1,1,1,1};                                    \
            _Pragma("unroll")                                                 \
            for (int _i = 0; _i < ITEMS; _i++)                                \
                if (_t0 + _i < T) _s[_i] = srow[_t0 + _i];                    \
            A = make_int4(_s[0], _s[1], _s[2], _s[3]);                        \
            B = make_int4(_s[4], _s[5], _s[6], _s[7]);                        \
        } } while (0)

    #define MKMASK(A, B, c, M) do {                                          \
        const int _t0 = (c) * CHUNK + tid * ITEMS;                           \
        const int _s[8] = {A.x, A.y, A.z, A.w, B.x, B.y, B.z, B.w};          \
        unsigned _tb = 0, _s0 = 0, _zm = 0;                                  \
        _Pragma("unroll")                                                    \
        for (int _i = 0; _i < ITEMS; _i++) {                                 \
            const unsigned _isT = (_s[_i] == 2);                             \
            const unsigned _inv = (_t0 + _i >= T);                           \
            _tb |= _isT << _i;                                               \
            _s0 |= (unsigned)(_s[_i] == 0) << _i;                            \
            _zm |= (_isT | _inv) << _i;                                      \
        }                                                                    \
        M = _tb | (_s0 << 8) | (_zm << 16); } while (0)

    // coalesced stage load: rows [klo, klo+min(cnt,CAPR)) -> 9 regs
    #define LDG_STAGE(klo, cnt, sreg) do {                                   \
        const int _nf = 3 * min((cnt), CAPR);                                \
        const float* _src = erow + (size_t)(klo) * 3;                        \
        _Pragma("unroll")                                                    \
        for (int _j = 0; _j < STREG; _j++) {                                 \
            const int _f = lane + 32 * _j;                                   \
            sreg[_j] = (_f < _nf) ? __ldg(_src + _f) : 0.f;                  \
        } } while (0)

    #define STS_STAGE(slot, sreg, cnt) do {                                  \
        float* _bp = &smb[slot][wid][0];                                     \
        const int _nf = 3 * min((cnt), CAPR);                                \
        _Pragma("unroll")                                                    \
        for (int _j = 0; _j < STREG; _j++) {                                 \
            const int _f = lane + 32 * _j;                                   \
            if (_f < _nf) _bp[(_f / 3) * 4 + (_f % 3)] = sreg[_j];           \
        } } while (0)

    // totals only; fallback LDG for rows >= CAPR (rare)
    #define CONSUME_TOT(slot, M, koff, klo, ax, ay, az) do {                 \
        const float* _bp = &smb[slot][wid][0];                               \
        const unsigned _tb = (M) & 0xffu, _s0 = ((M) >> 8) & 0xffu,          \
                       _zm = ((M) >> 16) & 0xffu;                            \
        ax = 0.f; ay = 0.f; az = 0.f;                                        \
        _Pragma("unroll")                                                    \
        for (int _i = 0; _i < ITEMS; _i++) {                                 \
            const int _row = (koff) + __popc(_tb & ((2u << _i) - 1u));       \
            float _ex, _ey, _ez;                                             \
            if (_row < CAPR) {                                               \
                const float4 _e = *reinterpret_cast<const float4*>(_bp + _row * 4); \
                _ex = _e.x; _ey = _e.y; _ez = _e.z;                          \
            } else {                                                         \
                const float* _p = erow + (size_t)((klo) + _row) * 3;         \
                _ex = __ldg(_p); _ey = __ldg(_p + 1); _ez = __ldg(_p + 2);   \
            }                                                                \
            const float _sp = ((_zm >> _i) & 1u) ? 0.f                       \
                            : (((_s0 >> _i) & 1u) ? sp0 : sp1);              \
            ax = fmaf(_ex, _sp, ax);                                         \
            ay = fmaf(_ey, _sp, ay);                                         \
            az = fmaf(_ez, _sp, az);                                         \
        } } while (0)

    // store with prefix recompute from smem
    #define STORE_CHUNK(c, slot, M, koff, klo, ex, ey, ez) do {              \
        const float* _bp = &smb[slot][wid][0];                               \
        const int _t0 = (c) * CHUNK + tid * ITEMS;                           \
        const unsigned _tb = (M) & 0xffu, _s0 = ((M) >> 8) & 0xffu,          \
                       _zm = ((M) >> 16) & 0xffu;                            \
        float _rx = (ex), _ry = (ey), _rz = (ez);                            \
        float _o[24];                                                        \
        _Pragma("unroll")                                                    \
        for (int _i = 0; _i < ITEMS; _i++) {                                 \
            const int _row = (koff) + __popc(_tb & ((2u << _i) - 1u));       \
            float _exv, _eyv, _ezv;                                          \
            if (_row < CAPR) {                                               \
                const float4 _e = *reinterpret_cast<const float4*>(_bp + _row * 4); \
                _exv = _e.x; _eyv = _e.y; _ezv = _e.z;                       \
            } else {                                                         \
                const float* _p = erow + (size_t)((klo) + _row) * 3;         \
                _exv = __ldg(_p); _eyv = __ldg(_p + 1); _ezv = __ldg(_p + 2);\
            }                                                                \
            const float _sp = ((_zm >> _i) & 1u) ? 0.f                       \
                            : (((_s0 >> _i) & 1u) ? sp0 : sp1);              \
            _rx = fmaf(_exv, _sp, _rx);                                      \
            _ry = fmaf(_eyv, _sp, _ry);                                      \
            _rz = fmaf(_ezv, _sp, _rz);                                      \
            _o[3*_i+0] = fmaf(DT, _rx, ox);                                  \
            _o[3*_i+1] = fmaf(DT, _ry, oy);                                  \
            _o[3*_i+2] = fmaf(DT, _rz, oz);                                  \
        }                                                                    \
        if (_t0 + ITEMS <= T) {                                              \
            float4* _q = reinterpret_cast<float4*>(xrow + (size_t)_t0 * 3);  \
            _Pragma("unroll")                                                \
            for (int _g = 0; _g < 6; _g++)                                   \
                __stwt(_q + _g, make_float4(_o[4*_g+0], _o[4*_g+1],          \
                                            _o[4*_g+2], _o[4*_g+3]));        \
        } else {                                                             \
            _Pragma("unroll")                                                \
            for (int _i = 0; _i < ITEMS; _i++)                               \
                if (_t0 + _i < T) {                                          \
                    float* _p = xrow + (size_t)(_t0 + _i) * 3;               \
                    _p[0] = _o[3*_i+0]; _p[1] = _o[3*_i+1]; _p[2] = _o[3*_i+2]; \
                }                                                            \
        } } while (0)

    #define GETMASK(c, M) do {                                               \
        if ((c) < P) { int4 _A, _B; LDST(c, _A, _B); MKMASK(_A, _B, c, M); } \
        else M = PADMASK; } while (0)

    // ================= prologue ==========================================
    unsigned mA, mB, mC, mD, mE, mF;
    GETMASK(0, mA); GETMASK(1, mB); GETMASK(2, mC);
    GETMASK(3, mD); GETMASK(4, mE); GETMASK(5, mF);

    int kloA, kloB, kloC, kloD, koffA, koffB, koffC, koffD, cntC, cntD, K;
    float sregA[STREG], sregB[STREG];
    {
        const int r0 = __popc(mA & 0xffu), r1 = __popc(mB & 0xffu);
        const int r2 = __popc(mC & 0xffu), r3 = __popc(mD & 0xffu);
        int a0 = r0, a1 = r1, a2 = r2, a3 = r3;
        #pragma unroll
        for (int d = 1; d < 32; d <<= 1) {
            const int y0 = __shfl_up_sync(0xffffffffu, a0, d);
            const int y1 = __shfl_up_sync(0xffffffffu, a1, d);
            const int y2 = __shfl_up_sync(0xffffffffu, a2, d);
            const int y3 = __shfl_up_sync(0xffffffffu, a3, d);
            if (lane >= d) { a0 += y0; a1 += y1; a2 += y2; a3 += y3; }
        }
        if (lane == 31) {
            s_a[wid][0] = (float)a0; s_a[wid][1] = (float)a1;
            s_a[wid][2] = (float)a2; s_a[wid][3] = (float)a3;
        }
        __syncthreads();
        int w0=0,w1=0,w2=0,w3=0, t0=0,t1=0,t2=0,t3=0, o0=0,o1=0,o2=0,o3=0;
        #pragma unroll
        for (int j = 0; j < NWARPS; j++) {
            const int v0=(int)s_a[j][0], v1=(int)s_a[j][1];
            const int v2=(int)s_a[j][2], v3=(int)s_a[j][3];
            if (j < wid) { w0+=v0; w1+=v1; w2+=v2; w3+=v3; }
            if (j == wid){ o0=v0; o1=v1; o2=v2; o3=v3; }
            t0+=v0; t1+=v1; t2+=v2; t3+=v3;
        }
        koffA = a0-r0; koffB = a1-r1; koffC = a2-r2; koffD = a3-r3;
        kloA = w0; kloB = t0+w1; kloC = t0+t1+w2; kloD = t0+t1+t2+w3;
        const int cntA = o0+1, cntB = o1+1;
        cntC = o2+1; cntD = o3+1;
        K = t0+t1+t2+t3;
        __syncthreads();
        // stage chunks 0,1 directly into slots 0,1 (one-time inline stall OK)
        if (0 < P) { LDG_STAGE(kloA, cntA, sregA); STS_STAGE(0, sregA, cntA); }
        if (1 < P) { LDG_STAGE(kloB, cntB, sregB); STS_STAGE(1, sregB, cntB); }
        // stage chunks 2,3 into relay registers (STS at body-0 top)
        if (2 < P) LDG_STAGE(kloC, cntC, sregA);
        if (3 < P) LDG_STAGE(kloD, cntD, sregB);
        __syncthreads();
    }

    float cx = 0.f, cy = 0.f, cz = 0.f;

    // ================= main loop: 2 chunks per body ========================
    for (int i = 0, par = 0; i < P; i += 2, par ^= 1) {
        // top: STS relay regs (chunks i+2, i+3) into the other slot pair
        if (i + 2 < P) STS_STAGE((par^1)*2 + 0, sregA, cntC);
        if (i + 3 < P) STS_STAGE((par^1)*2 + 1, sregB, cntD);

        // early state loads for chunks i+6, i+7
        int4 pa, pb, qa, qb;
        const bool h6 = (i + 6) < P, h7 = (i + 7) < P;
        if (h6) LDST(i + 6, pa, pb);
        if (h7) LDST(i + 7, qa, qb);

        // ---- first half: chunk i ----
        float ax, ay, az;
        CONSUME_TOT(par*2 + 0, mA, koffA, kloA, ax, ay, az);

        const int r4 = __popc(mE & 0xffu), r5 = __popc(mF & 0xffu);
        float sx = ax, sy = ay, sz = az, s4 = (float)r4, s5 = (float)r5;
        #pragma unroll
        for (int d = 1; d < 32; d <<= 1) {
            const float u0 = __shfl_up_sync(0xffffffffu, sx, d);
            const float u1 = __shfl_up_sync(0xffffffffu, sy, d);
            const float u2 = __shfl_up_sync(0xffffffffu, sz, d);
            const float u3 = __shfl_up_sync(0xffffffffu, s4, d);
            const float u4 = __shfl_up_sync(0xffffffffu, s5, d);
            if (lane >= d) { sx += u0; sy += u1; sz += u2; s4 += u3; s5 += u4; }
        }
        if (lane == 31) {
            s_a[wid][0] = sx; s_a[wid][1] = sy; s_a[wid][2] = sz;
            s_a[wid][3] = s4; s_a[wid][4] = s5;
        }
        __syncthreads();
        float wxe=0.f, wye=0.f, wze=0.f, txs=0.f, tys=0.f, tzs=0.f;
        int wr4=0, wr5=0, t4=0, t5=0, o4=0, o5=0;
        #pragma unroll
        for (int j = 0; j < NWARPS; j++) {
            const float fx=s_a[j][0], fy=s_a[j][1], fz=s_a[j][2];
            const int i4=(int)s_a[j][3], i5=(int)s_a[j][4];
            if (j < wid) { wxe+=fx; wye+=fy; wze+=fz; wr4+=i4; wr5+=i5; }
            if (j == wid){ o4=i4; o5=i5; }
            txs+=fx; tys+=fy; tzs+=fz; t4+=i4; t5+=i5;
        }
        const float ex = cx + wxe + (sx - ax);
        const float ey = cy + wye + (sy - ay);
        const float ez = cz + wze + (sz - az);
        const int kloE = K + wr4;
        const int kloF = K + t4 + wr5;
        const int koffE = (int)s4 - r4;
        const int koffF = (int)s5 - r5;
        const int cntE = o4 + 1, cntF = o5 + 1;
        cx += txs; cy += tys; cz += tzs;
        K  += t4 + t5;

        STORE_CHUNK(i, par*2 + 0, mA, koffA, kloA, ex, ey, ez);
        if (i + 4 < P) LDG_STAGE(kloE, cntE, sregA);

        // ---- second half: chunk i+1 ----
        if (i + 1 < P) {
            float bx, by, bz;
            CONSUME_TOT(par*2 + 1, mB, koffB, kloB, bx, by, bz);

            float ux = bx, uy = by, uz = bz;
            #pragma unroll
            for (int d = 1; d < 32; d <<= 1) {
                const float v0 = __shfl_up_sync(0xffffffffu, ux, d);
                const float v1 = __shfl_up_sync(0xffffffffu, uy, d);
                const float v2 = __shfl_up_sync(0xffffffffu, uz, d);
                if (lane >= d) { ux += v0; uy += v1; uz += v2; }
            }
            if (lane == 31) { s_b[wid][0]=ux; s_b[wid][1]=uy; s_b[wid][2]=uz; }
            __syncthreads();
            float wx2=0.f, wy2=0.f, wz2=0.f, tx2=0.f, ty2=0.f, tz2=0.f;
            #pragma unroll
            for (int j = 0; j < NWARPS; j++) {
                const float fx=s_b[j][0], fy=s_b[j][1], fz=s_b[j][2];
                if (j < wid) { wx2+=fx; wy2+=fy; wz2+=fz; }
                tx2+=fx; ty2+=fy; tz2+=fz;
            }
            const float ex2 = cx + wx2 + (ux - bx);
            const float ey2 = cy + wy2 + (uy - by);
            const float ez2 = cz + wz2 + (uz - bz);
            cx += tx2; cy += ty2; cz += tz2;

            STORE_CHUNK(i + 1, par*2 + 1, mB, koffB, kloB, ex2, ey2, ez2);
            if (i + 5 < P) LDG_STAGE(kloF, cntF, sregB);
        }

        // ---- rotate metadata ----
        mA = mC; kloA = kloC; koffA = koffC;
        mB = mD; kloB = kloD; koffB = koffD;
        mC = mE; kloC = kloE; koffC = koffE; cntC = cntE;
        mD = mF; kloD = kloF; koffD = koffF; cntD = cntF;
        if (h6) MKMASK(pa, pb, i + 6, mE); else mE = PADMASK;
        if (h7) MKMASK(qa, qb, i + 7, mF); else mF = PADMASK;
    }

    #undef LDST
    #undef MKMASK
    #undef LDG_STAGE
    #undef STS_STAGE
    #undef CONSUME_TOT
    #undef STORE_CHUNK
    #undef GETMASK
}

extern "C" void kernel_launch(void* const* d_in, const int* in_sizes, int n_in,
                              void* d_out, int out_size)
{
    const int*   states = (const int*)  d_in[0];
    const float* e0s    = (const float*)d_in[1];
    const float* sp0    = (const float*)d_in[2];
    const float* sp1    = (const float*)d_in[3];
    const float* x0     = (const float*)d_in[4];
    float*       X      = (float*)d_out;

    const int B = in_sizes[2];            // speed_0 has B elements
    const int T = in_sizes[0] / B;        // states is (B, T)
    const int P = (T + CHUNK - 1) / CHUNK;

    traj_scan_kernel<<<B, THREADS>>>(states, e0s, sp0, sp1, x0, X, T, P);
}

// round 16
// speedup vs baseline: 1.0003x; 1.0003x over previous
#include <cuda_runtime.h>
#include <cuda_bf16.h>
#include <stdint.h>

#define THREADS 256
#define ITEMS   8
#define CHUNK   (THREADS * ITEMS)   // 2048
#define NWARPS  (THREADS / 32)      // 8
#define CAPR    95                  // staged rows per warp-chunk (16B padded)
#define STREG   9                   // 9*32 = 288 >= 3*CAPR floats
#define PADMASK 0x00FF0000u

__global__ __launch_bounds__(THREADS, 2)
void traj_scan_kernel(const int*   __restrict__ states,
                      const float* __restrict__ e0s,
                      const float* __restrict__ speed0,
                      const float* __restrict__ speed1,
                      const float* __restrict__ x0,
                      float*       __restrict__ X,
                      int T, int P)
{
    __shared__ __align__(16) float smb[4][NWARPS][CAPR * 4];  // 48640 B
    __shared__ float s_a[NWARPS][5];
    __shared__ float s_b[NWARPS][3];

    const int b = blockIdx.x;
    const int*   srow = states + (size_t)b * T;
    const float* erow = e0s    + (size_t)b * (T + 1) * 3;
    float*       xrow = X      + (size_t)b * T * 3;

    const float sp0 = speed0[b], sp1 = speed1[b];
    const float ox = x0[3*b+0], oy = x0[3*b+1], oz = x0[3*b+2];
    const float DT = 0.1f;
    const int tid = threadIdx.x, lane = tid & 31, wid = tid >> 5;

    #define LDST(c, A, B) do {                                                \
        const int _t0 = (c) * CHUNK + tid * ITEMS;                            \
        if (_t0 + ITEMS <= T) {                                               \
            A = *reinterpret_cast<const int4*>(srow + _t0);                   \
            B = *reinterpret_cast<const int4*>(srow + _t0 + 4);               \
        } else {                                                              \
            int _s[8] = {1,1,1,1,1,1,1,1};                                    \
            _Pragma("unroll")                                                 \
            for (int _i = 0; _i < ITEMS; _i++)                                \
                if (_t0 + _i < T) _s[_i] = srow[_t0 + _i];                    \
            A = make_int4(_s[0], _s[1], _s[2], _s[3]);                        \
            B = make_int4(_s[4], _s[5], _s[6], _s[7]);                        \
        } } while (0)

    #define MKMASK(A, B, c, M) do {                                          \
        const int _t0 = (c) * CHUNK + tid * ITEMS;                           \
        const int _s[8] = {A.x, A.y, A.z, A.w, B.x, B.y, B.z, B.w};          \
        unsigned _tb = 0, _s0 = 0, _zm = 0;                                  \
        _Pragma("unroll")                                                    \
        for (int _i = 0; _i < ITEMS; _i++) {                                 \
            const unsigned _isT = (_s[_i] == 2);                             \
            const unsigned _inv = (_t0 + _i >= T);                           \
            _tb |= _isT << _i;                                               \
            _s0 |= (unsigned)(_s[_i] == 0) << _i;                            \
            _zm |= (_isT | _inv) << _i;                                      \
        }                                                                    \
        M = _tb | (_s0 << 8) | (_zm << 16); } while (0)

    // coalesced stage load: rows [klo, klo+min(cnt,CAPR)) -> 9 regs
    #define LDG_STAGE(klo, cnt, sreg) do {                                   \
        const int _nf = 3 * min((cnt), CAPR);                                \
        const float* _src = erow + (size_t)(klo) * 3;                        \
        _Pragma("unroll")                                                    \
        for (int _j = 0; _j < STREG; _j++) {                                 \
            const int _f = lane + 32 * _j;                                   \
            sreg[_j] = (_f < _nf) ? __ldg(_src + _f) : 0.f;                  \
        } } while (0)

    #define STS_STAGE(slot, sreg, cnt) do {                                  \
        float* _bp = &smb[slot][wid][0];                                     \
        const int _nf = 3 * min((cnt), CAPR);                                \
        _Pragma("unroll")                                                    \
        for (int _j = 0; _j < STREG; _j++) {                                 \
            const int _f = lane + 32 * _j;                                   \
            if (_f < _nf) _bp[(_f / 3) * 4 + (_f % 3)] = sreg[_j];           \
        } } while (0)

    // totals only; fallback LDG for rows >= CAPR (rare)
    #define CONSUME_TOT(slot, M, koff, klo, ax, ay, az) do {                 \
        const float* _bp = &smb[slot][wid][0];                               \
        const unsigned _tb = (M) & 0xffu, _s0 = ((M) >> 8) & 0xffu,          \
                       _zm = ((M) >> 16) & 0xffu;                            \
        ax = 0.f; ay = 0.f; az = 0.f;                                        \
        _Pragma("unroll")                                                    \
        for (int _i = 0; _i < ITEMS; _i++) {                                 \
            const int _row = (koff) + __popc(_tb & ((2u << _i) - 1u));       \
            float _ex, _ey, _ez;                                             \
            if (_row < CAPR) {                                               \
                const float4 _e = *reinterpret_cast<const float4*>(_bp + _row * 4); \
                _ex = _e.x; _ey = _e.y; _ez = _e.z;                          \
            } else {                                                         \
                const float* _p = erow + (size_t)((klo) + _row) * 3;         \
                _ex = __ldg(_p); _ey = __ldg(_p + 1); _ez = __ldg(_p + 2);   \
            }                                                                \
            const float _sp = ((_zm >> _i) & 1u) ? 0.f                       \
                            : (((_s0 >> _i) & 1u) ? sp0 : sp1);              \
            ax = fmaf(_ex, _sp, ax);                                         \
            ay = fmaf(_ey, _sp, ay);                                         \
            az = fmaf(_ez, _sp, az);                                         \
        } } while (0)

    // store with prefix recompute from smem
    #define STORE_CHUNK(c, slot, M, koff, klo, ex, ey, ez) do {              \
        const float* _bp = &smb[slot][wid][0];                               \
        const int _t0 = (c) * CHUNK + tid * ITEMS;                           \
        const unsigned _tb = (M) & 0xffu, _s0 = ((M) >> 8) & 0xffu,          \
                       _zm = ((M) >> 16) & 0xffu;                            \
        float _rx = (ex), _ry = (ey), _rz = (ez);                            \
        float _o[24];                                                        \
        _Pragma("unroll")                                                    \
        for (int _i = 0; _i < ITEMS; _i++) {                                 \
            const int _row = (koff) + __popc(_tb & ((2u << _i) - 1u));       \
            float _exv, _eyv, _ezv;                                          \
            if (_row < CAPR) {                                               \
                const float4 _e = *reinterpret_cast<const float4*>(_bp + _row * 4); \
                _exv = _e.x; _eyv = _e.y; _ezv = _e.z;                       \
            } else {                                                         \
                const float* _p = erow + (size_t)((klo) + _row) * 3;         \
                _exv = __ldg(_p); _eyv = __ldg(_p + 1); _ezv = __ldg(_p + 2);\
            }                                                                \
            const float _sp = ((_zm >> _i) & 1u) ? 0.f                       \
                            : (((_s0 >> _i) & 1u) ? sp0 : sp1);              \
            _rx = fmaf(_exv, _sp, _rx);                                      \
            _ry = fmaf(_eyv, _sp, _ry);                                      \
            _rz = fmaf(_ezv, _sp, _rz);                                      \
            _o[3*_i+0] = fmaf(DT, _rx, ox);                                  \
            _o[3*_i+1] = fmaf(DT, _ry, oy);                                  \
            _o[3*_i+2] = fmaf(DT, _rz, oz);                                  \
        }                                                                    \
        if (_t0 + ITEMS <= T) {                                              \
            float4* _q = reinterpret_cast<float4*>(xrow + (size_t)_t0 * 3);  \
            _Pragma("unroll")                                                \
            for (int _g = 0; _g < 6; _g++)                                   \
                __stwt(_q + _g, make_float4(_o[4*_g+0], _o[4*_g+1],          \
                                            _o[4*_g+2], _o[4*_g+3]));        \
        } else {                                                             \
            _Pragma("unroll")                                                \
            for (int _i = 0; _i < ITEMS; _i++)                               \
                if (_t0 + _i < T) {                                          \
                    float* _p = xrow + (size_t)(_t0 + _i) * 3;               \
                    _p[0] = _o[3*_i+0]; _p[1] = _o[3*_i+1]; _p[2] = _o[3*_i+2]; \
                }                                                            \
        } } while (0)

    #define GETMASK(c, M) do {                                               \
        if ((c) < P) { int4 _A, _B; LDST(c, _A, _B); MKMASK(_A, _B, c, M); } \
        else M = PADMASK; } while (0)

    // ================= prologue ==========================================
    unsigned mA, mB, mC, mD, mE, mF;
    GETMASK(0, mA); GETMASK(1, mB); GETMASK(2, mC);
    GETMASK(3, mD); GETMASK(4, mE); GETMASK(5, mF);

    int kloA, kloB, kloC, kloD, koffA, koffB, koffC, koffD, cntC, cntD, K;
    float sregA[STREG], sregB[STREG];
    {
        const int r0 = __popc(mA & 0xffu), r1 = __popc(mB & 0xffu);
        const int r2 = __popc(mC & 0xffu), r3 = __popc(mD & 0xffu);
        int a0 = r0, a1 = r1, a2 = r2, a3 = r3;
        #pragma unroll
        for (int d = 1; d < 32; d <<= 1) {
            const int y0 = __shfl_up_sync(0xffffffffu, a0, d);
            const int y1 = __shfl_up_sync(0xffffffffu, a1, d);
            const int y2 = __shfl_up_sync(0xffffffffu, a2, d);
            const int y3 = __shfl_up_sync(0xffffffffu, a3, d);
            if (lane >= d) { a0 += y0; a1 += y1; a2 += y2; a3 += y3; }
        }
        if (lane == 31) {
            s_a[wid][0] = (float)a0; s_a[wid][1] = (float)a1;
            s_a[wid][2] = (float)a2; s_a[wid][3] = (float)a3;
        }
        __syncthreads();
        int w0=0,w1=0,w2=0,w3=0, t0=0,t1=0,t2=0,t3=0, o0=0,o1=0,o2=0,o3=0;
        #pragma unroll
        for (int j = 0; j < NWARPS; j++) {
            const int v0=(int)s_a[j][0], v1=(int)s_a[j][1];
            const int v2=(int)s_a[j][2], v3=(int)s_a[j][3];
            if (j < wid) { w0+=v0; w1+=v1; w2+=v2; w3+=v3; }
            if (j == wid){ o0=v0; o1=v1; o2=v2; o3=v3; }
            t0+=v0; t1+=v1; t2+=v2; t3+=v3;
        }
        koffA = a0-r0; koffB = a1-r1; koffC = a2-r2; koffD = a3-r3;
        kloA = w0; kloB = t0+w1; kloC = t0+t1+w2; kloD = t0+t1+t2+w3;
        const int cntA = o0+1, cntB = o1+1;
        cntC = o2+1; cntD = o3+1;
        K = t0+t1+t2+t3;
        __syncthreads();
        // stage chunks 0,1 directly into slots 0,1 (one-time inline stall OK)
        if (0 < P) { LDG_STAGE(kloA, cntA, sregA); STS_STAGE(0, sregA, cntA); }
        if (1 < P) { LDG_STAGE(kloB, cntB, sregB); STS_STAGE(1, sregB, cntB); }
        // stage chunks 2,3 into relay registers (STS at body-0 top)
        if (2 < P) LDG_STAGE(kloC, cntC, sregA);
        if (3 < P) LDG_STAGE(kloD, cntD, sregB);
        __syncthreads();
    }

    float cx = 0.f, cy = 0.f, cz = 0.f;

    // ================= main loop: 2 chunks per body ========================
    for (int i = 0, par = 0; i < P; i += 2, par ^= 1) {
        // top: STS relay regs (chunks i+2, i+3) into the other slot pair
        if (i + 2 < P) STS_STAGE((par^1)*2 + 0, sregA, cntC);
        if (i + 3 < P) STS_STAGE((par^1)*2 + 1, sregB, cntD);

        // early state loads for chunks i+6, i+7
        int4 pa, pb, qa, qb;
        const bool h6 = (i + 6) < P, h7 = (i + 7) < P;
        if (h6) LDST(i + 6, pa, pb);
        if (h7) LDST(i + 7, qa, qb);

        // ---- first half: chunk i ----
        float ax, ay, az;
        CONSUME_TOT(par*2 + 0, mA, koffA, kloA, ax, ay, az);

        const int r4 = __popc(mE & 0xffu), r5 = __popc(mF & 0xffu);
        float sx = ax, sy = ay, sz = az, s4 = (float)r4, s5 = (float)r5;
        #pragma unroll
        for (int d = 1; d < 32; d <<= 1) {
            const float u0 = __shfl_up_sync(0xffffffffu, sx, d);
            const float u1 = __shfl_up_sync(0xffffffffu, sy, d);
            const float u2 = __shfl_up_sync(0xffffffffu, sz, d);
            const float u3 = __shfl_up_sync(0xffffffffu, s4, d);
            const float u4 = __shfl_up_sync(0xffffffffu, s5, d);
            if (lane >= d) { sx += u0; sy += u1; sz += u2; s4 += u3; s5 += u4; }
        }
        if (lane == 31) {
            s_a[wid][0] = sx; s_a[wid][1] = sy; s_a[wid][2] = sz;
            s_a[wid][3] = s4; s_a[wid][4] = s5;
        }
        __syncthreads();
        float wxe=0.f, wye=0.f, wze=0.f, txs=0.f, tys=0.f, tzs=0.f;
        int wr4=0, wr5=0, t4=0, t5=0, o4=0, o5=0;
        #pragma unroll
        for (int j = 0; j < NWARPS; j++) {
            const float fx=s_a[j][0], fy=s_a[j][1], fz=s_a[j][2];
            const int i4=(int)s_a[j][3], i5=(int)s_a[j][4];
            if (j < wid) { wxe+=fx; wye+=fy; wze+=fz; wr4+=i4; wr5+=i5; }
            if (j == wid){ o4=i4; o5=i5; }
            txs+=fx; tys+=fy; tzs+=fz; t4+=i4; t5+=i5;
        }
        const float ex = cx + wxe + (sx - ax);
        const float ey = cy + wye + (sy - ay);
        const float ez = cz + wze + (sz - az);
        const int kloE = K + wr4;
        const int kloF = K + t4 + wr5;
        const int koffE = (int)s4 - r4;
        const int koffF = (int)s5 - r5;
        const int cntE = o4 + 1, cntF = o5 + 1;
        cx += txs; cy += tys; cz += tzs;
        K  += t4 + t5;

        STORE_CHUNK(i, par*2 + 0, mA, koffA, kloA, ex, ey, ez);
        if (i + 4 < P) LDG_STAGE(kloE, cntE, sregA);

        // ---- second half: chunk i+1 ----
        if (i + 1 < P) {
            float bx, by, bz;
            CONSUME_TOT(par*2 + 1, mB, koffB, kloB, bx, by, bz);

            float ux = bx, uy = by, uz = bz;
            #pragma unroll
            for (int d = 1; d < 32; d <<= 1) {
                const float v0 = __shfl_up_sync(0xffffffffu, ux, d);
                const float v1 = __shfl_up_sync(0xffffffffu, uy, d);
                const float v2 = __shfl_up_sync(0xffffffffu, uz, d);
                if (lane >= d) { ux += v0; uy += v1; uz += v2; }
            }
            if (lane == 31) { s_b[wid][0]=ux; s_b[wid][1]=uy; s_b[wid][2]=uz; }
            __syncthreads();
            float wx2=0.f, wy2=0.f, wz2=0.f, tx2=0.f, ty2=0.f, tz2=0.f;
            #pragma unroll
            for (int j = 0; j < NWARPS; j++) {
                const float fx=s_b[j][0], fy=s_b[j][1], fz=s_b[j][2];
                if (j < wid) { wx2+=fx; wy2+=fy; wz2+=fz; }
                tx2+=fx; ty2+=fy; tz2+=fz;
            }
            const float ex2 = cx + wx2 + (ux - bx);
            const float ey2 = cy + wy2 + (uy - by);
            const float ez2 = cz + wz2 + (uz - bz);
            cx += tx2; cy += ty2; cz += tz2;

            STORE_CHUNK(i + 1, par*2 + 1, mB, koffB, kloB, ex2, ey2, ez2);
            if (i + 5 < P) LDG_STAGE(kloF, cntF, sregB);
        }

        // ---- rotate metadata ----
        mA = mC; kloA = kloC; koffA = koffC;
        mB = mD; kloB = kloD; koffB = koffD;
        mC = mE; kloC = kloE; koffC = koffE; cntC = cntE;
        mD = mF; kloD = kloF; koffD = koffF; cntD = cntF;
        if (h6) MKMASK(pa, pb, i + 6, mE); else mE = PADMASK;
        if (h7) MKMASK(qa, qb, i + 7, mF); else mF = PADMASK;
    }

    #undef LDST
    #undef MKMASK
    #undef LDG_STAGE
    #undef STS_STAGE
    #undef CONSUME_TOT
    #undef STORE_CHUNK
    #undef GETMASK
}

extern "C" void kernel_launch(void* const* d_in, const int* in_sizes, int n_in,
                              void* d_out, int out_size)
{
    const int*   states = (const int*)  d_in[0];
    const float* e0s    = (const float*)d_in[1];
    const float* sp0    = (const float*)d_in[2];
    const float* sp1    = (const float*)d_in[3];
    const float* x0     = (const float*)d_in[4];
    float*       X      = (float*)d_out;

    const int B = in_sizes[2];            // speed_0 has B elements
    const int T = in_sizes[0] / B;        // states is (B, T)
    const int P = (T + CHUNK - 1) / CHUNK;

    traj_scan_kernel<<<B, THREADS>>>(states, e0s, sp0, sp1, x0, X, T, P);
}